// round 13
// baseline (speedup 1.0000x reference)
#include <cuda_runtime.h>
#include <cstdint>

// ---------------------------------------------------------------------------
// Problem constants
// ---------------------------------------------------------------------------
#define NB     128          // b = B*nw
#define NTOK   343          // n
#define CDIM   512          // c
#define NH     16           // heads
#define HD     32           // head dim
#define MROWS  (NB * NTOK)  // 43904 = 343 * 128
#define SCALE_F 0.17677669529663687f   // 32^-0.5
#define BMSTR  384          // padded bias/mask row stride (covers col<=383 reads)
#define VTSTR  384          // padded V^T row stride (keys), 16B-aligned rows

// ---------------------------------------------------------------------------
// Scratch (device globals; no allocations allowed)
// ---------------------------------------------------------------------------
__device__ float g_k[(size_t)NB * NH * NTOK * HD];        // [b][h][n][32] d-permuted, tf32
__device__ float g_vT[(size_t)NB * NH * HD * VTSTR];      // [b][h][d][n] transposed, tf32
__device__ float g_bias[(size_t)NH * NTOK * BMSTR];       // [h][i][j] stride 384
__device__ float g_maskp[(size_t)64 * NTOK * BMSTR];      // [wi][i][j] stride 384
__device__ float g_o[(size_t)MROWS * CDIM];               // [b*n][c] head-major cols

// ---------------------------------------------------------------------------
// Kernel 1a: relative position bias  bias[h][i][j] = rpb[rel(i,j)*16 + h]
// ---------------------------------------------------------------------------
__global__ void bias_kernel(const float* __restrict__ rpb) {
    int idx = blockIdx.x * 256 + threadIdx.x;
    if (idx >= NTOK * BMSTR) return;
    int i = idx / BMSTR, j = idx % BMSTR;
    if (j >= NTOK) {
#pragma unroll
        for (int h = 0; h < NH; h++)
            g_bias[(size_t)h * NTOK * BMSTR + idx] = 0.f;
        return;
    }
    int di = i / 49, hi = (i / 7) % 7, wi = i % 7;
    int dj = j / 49, hj = (j / 7) % 7, wj = j % 7;
    int rel = (di - dj + 6) * 169 + (hi - hj + 6) * 13 + (wi - wj + 6);
    const float* src = rpb + rel * NH;
#pragma unroll
    for (int h = 0; h < NH; h++)
        g_bias[(size_t)h * NTOK * BMSTR + idx] = src[h];
}

// ---------------------------------------------------------------------------
// Kernel 1b: repack mask into padded stride-384 table
// ---------------------------------------------------------------------------
__global__ void mask_copy_kernel(const float* __restrict__ mask) {
    int idx = blockIdx.x * 256 + threadIdx.x;
    if (idx >= 64 * NTOK * BMSTR) return;
    int w = idx / (NTOK * BMSTR);
    int r = idx % (NTOK * BMSTR);
    int i = r / BMSTR, j = r % BMSTR;
    g_maskp[idx] = (j < NTOK) ? mask[((size_t)w * NTOK + i) * NTOK + j] : 0.f;
}

// ---------------------------------------------------------------------------
// tf32 / cp.async helpers
// ---------------------------------------------------------------------------
__device__ __forceinline__ float to_tf32(float x) {
    asm("cvt.rna.tf32.f32 %0, %0;" : "+f"(x));
    return x;
}

__device__ __forceinline__ void mma_tf32(float& d0, float& d1, float& d2, float& d3,
                                         uint32_t a0, uint32_t a1, uint32_t a2, uint32_t a3,
                                         uint32_t b0, uint32_t b1) {
    asm volatile(
        "mma.sync.aligned.m16n8k8.row.col.f32.tf32.tf32.f32 "
        "{%0,%1,%2,%3},{%4,%5,%6,%7},{%8,%9},{%0,%1,%2,%3};"
        : "+f"(d0), "+f"(d1), "+f"(d2), "+f"(d3)
        : "r"(a0), "r"(a1), "r"(a2), "r"(a3), "r"(b0), "r"(b1));
}

__device__ __forceinline__ void cp16(uint32_t dst, const void* src) {
    asm volatile("cp.async.cg.shared.global [%0], [%1], 16;" :: "r"(dst), "l"(src));
}
__device__ __forceinline__ void cp_commit() {
    asm volatile("cp.async.commit_group;");
}
__device__ __forceinline__ void cp_wait0() {
    asm volatile("cp.async.wait_group 0;");
}

// within-8-group column permutation so B-frag pairs (t, t+4) sit adjacent
__device__ __forceinline__ int dperm(int d) {
    return (d & 24) | ((d & 3) << 1) | ((d >> 2) & 1);
}

// ---------------------------------------------------------------------------
// Kernel 2/4: tf32 tensor-core GEMM  C[M,N] = A[M,K] * B[N,K]^T
// mode 0 epilogue: K -> g_k (d-permuted), V -> g_vT (transposed), tf32-rounded
// mode 1 epilogue: Cout = acc + cbias, A = g_o
// ---------------------------------------------------------------------------
#define GSTR 136

__global__ __launch_bounds__(256, 2)
void gemm_tf32(const float* __restrict__ Ain,
               const float* __restrict__ Bw,
               float* __restrict__ Cout,
               const float* __restrict__ cbias,
               int mode) {
    const float* A = (mode == 1) ? g_o : Ain;

    __shared__ float As[2][16][GSTR];
    __shared__ float Bs[2][16][GSTR];

    const int tid  = threadIdx.x;
    const int warp = tid >> 5;
    const int lane = tid & 31;
    const int qr   = lane >> 2;   // 0..7
    const int qk   = lane & 3;    // 0..3
    const int warpM = (warp & 1) * 64;
    const int warpN = (warp >> 1) * 32;

    const int rowBase = blockIdx.y * 128;
    const int colBase = blockIdx.x * 128;

    const int m0 = tid >> 2;
    const int kq = tid & 3;
    const float* a0p = A  + (size_t)(rowBase + m0) * CDIM + kq * 4;
    const float* a1p = a0p + (size_t)64 * CDIM;
    const float* b0p = Bw + (size_t)(colBase + m0) * CDIM + kq * 4;
    const float* b1p = b0p + (size_t)64 * CDIM;
    const int swS = kq << 3;

    float acc[4][4][4];
#pragma unroll
    for (int mt = 0; mt < 4; mt++)
#pragma unroll
        for (int nt = 0; nt < 4; nt++)
#pragma unroll
            for (int r = 0; r < 4; r++) acc[mt][nt][r] = 0.f;

    float4 ra0, ra1, rb0, rb1;

    ra0 = *(const float4*)(a0p); ra1 = *(const float4*)(a1p);
    rb0 = *(const float4*)(b0p); rb1 = *(const float4*)(b1p);
    {
        float av0[4] = {ra0.x, ra0.y, ra0.z, ra0.w};
        float av1[4] = {ra1.x, ra1.y, ra1.z, ra1.w};
        float bv0[4] = {rb0.x, rb0.y, rb0.z, rb0.w};
        float bv1[4] = {rb1.x, rb1.y, rb1.z, rb1.w};
#pragma unroll
        for (int j = 0; j < 4; j++) {
            As[0][kq * 4 + j][m0 ^ swS]        = to_tf32(av0[j]);
            As[0][kq * 4 + j][(m0 + 64) ^ swS] = to_tf32(av1[j]);
            Bs[0][kq * 4 + j][m0 ^ swS]        = to_tf32(bv0[j]);
            Bs[0][kq * 4 + j][(m0 + 64) ^ swS] = to_tf32(bv1[j]);
        }
    }
    __syncthreads();

    for (int it = 0; it < 32; ++it) {
        const int buf = it & 1;
        if (it < 31) {
            const int off = (it + 1) * 16;
            ra0 = *(const float4*)(a0p + off); ra1 = *(const float4*)(a1p + off);
            rb0 = *(const float4*)(b0p + off); rb1 = *(const float4*)(b1p + off);
        }

#pragma unroll
        for (int ks = 0; ks < 16; ks += 8) {
            uint32_t af[4][4], bf[4][2];
            const int kA = ks + qk;
            const int kB = ks + qk + 4;
            const int sA = ((kA >> 2) << 3);
            const int sB = ((kB >> 2) << 3);
#pragma unroll
            for (int mt = 0; mt < 4; mt++) {
                const int m = warpM + mt * 16 + qr;
                af[mt][0] = __float_as_uint(As[buf][kA][m ^ sA]);
                af[mt][1] = __float_as_uint(As[buf][kA][(m + 8) ^ sA]);
                af[mt][2] = __float_as_uint(As[buf][kB][m ^ sB]);
                af[mt][3] = __float_as_uint(As[buf][kB][(m + 8) ^ sB]);
            }
#pragma unroll
            for (int nt = 0; nt < 4; nt++) {
                const int nn = warpN + nt * 8 + qr;
                bf[nt][0] = __float_as_uint(Bs[buf][kA][nn ^ sA]);
                bf[nt][1] = __float_as_uint(Bs[buf][kB][nn ^ sB]);
            }
#pragma unroll
            for (int mt = 0; mt < 4; mt++)
#pragma unroll
                for (int nt = 0; nt < 4; nt++)
                    mma_tf32(acc[mt][nt][0], acc[mt][nt][1], acc[mt][nt][2], acc[mt][nt][3],
                             af[mt][0], af[mt][1], af[mt][2], af[mt][3],
                             bf[nt][0], bf[nt][1]);
        }

        if (it < 31) {
            const int nbuf = buf ^ 1;
            float av0[4] = {ra0.x, ra0.y, ra0.z, ra0.w};
            float av1[4] = {ra1.x, ra1.y, ra1.z, ra1.w};
            float bv0[4] = {rb0.x, rb0.y, rb0.z, rb0.w};
            float bv1[4] = {rb1.x, rb1.y, rb1.z, rb1.w};
#pragma unroll
            for (int j = 0; j < 4; j++) {
                As[nbuf][kq * 4 + j][m0 ^ swS]        = to_tf32(av0[j]);
                As[nbuf][kq * 4 + j][(m0 + 64) ^ swS] = to_tf32(av1[j]);
                Bs[nbuf][kq * 4 + j][m0 ^ swS]        = to_tf32(bv0[j]);
                Bs[nbuf][kq * 4 + j][(m0 + 64) ^ swS] = to_tf32(bv1[j]);
            }
        }
        __syncthreads();
    }

    if (mode == 0) {
        // K -> g_k (d-permuted within 8-groups); V -> g_vT (transposed). tf32-rounded.
#pragma unroll
        for (int mt = 0; mt < 4; mt++) {
            const int row = rowBase + warpM + mt * 16 + qr;
            const int bb0 = row / NTOK;
            const int nn0 = row - bb0 * NTOK;
            const int bb8 = (row + 8) / NTOK;
            const int nn8 = (row + 8) - bb8 * NTOK;
#pragma unroll
            for (int nt = 0; nt < 4; nt++) {
                const int col = colBase + warpN + nt * 8 + qk * 2;
                const int d   = col & 31;
                const float v0 = to_tf32(acc[mt][nt][0]);
                const float v1 = to_tf32(acc[mt][nt][1]);
                const float v2 = to_tf32(acc[mt][nt][2]);
                const float v3 = to_tf32(acc[mt][nt][3]);
                if (col < 512) {
                    const int hv = col >> 5;
                    const int d0p = dperm(d), d1p = dperm(d + 1);
                    size_t base0 = ((((size_t)bb0 * NH + hv) * NTOK) + nn0) * HD;
                    size_t base8 = ((((size_t)bb8 * NH + hv) * NTOK) + nn8) * HD;
                    g_k[base0 + d0p] = v0;  g_k[base0 + d1p] = v1;
                    g_k[base8 + d0p] = v2;  g_k[base8 + d1p] = v3;
                } else {
                    const int hv = (col - 512) >> 5;
                    size_t r0v = (((size_t)bb0 * NH + hv) * HD + d) * VTSTR;
                    size_t r1v = (((size_t)bb0 * NH + hv) * HD + d + 1) * VTSTR;
                    size_t r0w = (((size_t)bb8 * NH + hv) * HD + d) * VTSTR;
                    size_t r1w = (((size_t)bb8 * NH + hv) * HD + d + 1) * VTSTR;
                    g_vT[r0v + nn0] = v0;  g_vT[r1v + nn0] = v1;
                    g_vT[r0w + nn8] = v2;  g_vT[r1w + nn8] = v3;
                }
            }
        }
    } else {
#pragma unroll
        for (int mt = 0; mt < 4; mt++) {
            const int row = rowBase + warpM + mt * 16 + qr;
#pragma unroll
            for (int nt = 0; nt < 4; nt++) {
                const int col = colBase + warpN + nt * 8 + qk * 2;
                const float b0v = cbias[col], b1v = cbias[col + 1];
                *(float2*)(Cout + (size_t)row * CDIM + col) =
                    make_float2(acc[mt][nt][0] + b0v, acc[mt][nt][1] + b1v);
                *(float2*)(Cout + (size_t)(row + 8) * CDIM + col) =
                    make_float2(acc[mt][nt][2] + b0v, acc[mt][nt][3] + b1v);
            }
        }
    }
}

// ---------------------------------------------------------------------------
// Kernel 3: tensor-core flash attention, cp.async double-buffered.
// grid (b*h = 2048, 3 query tiles of 128), block 128 (4 warps, 32 q/warp).
// Each warp owns TWO m16 query tiles -> every K/V B-frag LDS feeds 2 MMAs.
// P never touches smem (S C-frags -> PV A-frags in registers).
// smem: K 2*[64][40] + V^T 2*[32][72] = 38912 B
// ---------------------------------------------------------------------------
#define KSTR 40
#define VSTR 72
#define ATT_SMEM ((2 * 64 * KSTR + 2 * 32 * VSTR) * 4)

__global__ __launch_bounds__(128, 3)
void attn_mma(const float* __restrict__ qg) {
    const int bh = blockIdx.x;
    const int bb = bh >> 4, h = bh & 15;
    const int Bi = bb >> 6, wi = bb & 63;
    const int qbase = blockIdx.y * 128;
    const int tid = threadIdx.x, warp = tid >> 5, lane = tid & 31;
    const int g = lane >> 2, t = lane & 3;

    extern __shared__ float sm[];
    float* KsA[2] = {sm, sm + 64 * KSTR};
    float* VsA[2] = {sm + 2 * 64 * KSTR, sm + 2 * 64 * KSTR + 32 * VSTR};

    // 4 query row-groups per warp: j=0,1 -> M-tile 0 (rows base+g, base+g+8),
    //                              j=2,3 -> M-tile 1 (rows base+16+g, +24)
    const int rbase = qbase + warp * 32;
    int rr[4], rc[4];
#pragma unroll
    for (int j = 0; j < 4; j++) {
        rr[j] = rbase + j * 8 + g;
        rc[j] = min(rr[j], NTOK - 1);
    }

    // Q fragments for both M-tiles (registers, pre-scaled)
    uint32_t qa[2][4][4];
#pragma unroll
    for (int mt = 0; mt < 2; mt++) {
        const float* q0p = qg + (((size_t)Bi * NH + h) * NTOK + rc[2 * mt]) * HD;
        const float* q1p = qg + (((size_t)Bi * NH + h) * NTOK + rc[2 * mt + 1]) * HD;
#pragma unroll
        for (int ks = 0; ks < 4; ks++) {
            qa[mt][ks][0] = __float_as_uint(to_tf32(q0p[ks * 8 + t] * SCALE_F));
            qa[mt][ks][1] = __float_as_uint(to_tf32(q1p[ks * 8 + t] * SCALE_F));
            qa[mt][ks][2] = __float_as_uint(to_tf32(q0p[ks * 8 + t + 4] * SCALE_F));
            qa[mt][ks][3] = __float_as_uint(to_tf32(q1p[ks * 8 + t + 4] * SCALE_F));
        }
    }

    const float* bbase = g_bias  + (size_t)h  * NTOK * BMSTR;
    const float* mbase = g_maskp + (size_t)wi * NTOK * BMSTR;
    int boff[4];
#pragma unroll
    for (int j = 0; j < 4; j++) boff[j] = rc[j] * BMSTR;

    const float* kb  = g_k  + ((size_t)bb * NH + h) * NTOK * HD;
    const float* vtb = g_vT + ((size_t)bb * NH + h) * HD * VTSTR;

    // staging (128 threads): K = 64 rows x 32 floats (16 floats/thread);
    //                        V^T = 32 rows x 64 floats (16 floats/thread)
    const int kln = tid >> 1, klp = (tid & 1) * 16;
    const int vrow = tid >> 2, vseg = (tid & 3) * 16;

    const uint32_t ksm[2] = {(uint32_t)__cvta_generic_to_shared(KsA[0] + kln * KSTR + klp),
                             (uint32_t)__cvta_generic_to_shared(KsA[1] + kln * KSTR + klp)};
    const uint32_t vsm[2] = {(uint32_t)__cvta_generic_to_shared(VsA[0] + vrow * VSTR + vseg),
                             (uint32_t)__cvta_generic_to_shared(VsA[1] + vrow * VSTR + vseg)};

    float rm[4], l[4];
#pragma unroll
    for (int j = 0; j < 4; j++) { rm[j] = -1e30f; l[j] = 0.f; }
    float oacc[2][4][4];
#pragma unroll
    for (int mt = 0; mt < 2; mt++)
#pragma unroll
        for (int df = 0; df < 4; df++)
#pragma unroll
            for (int r = 0; r < 4; r++) oacc[mt][df][r] = 0.f;

    // prologue: stage chunk 0 into buffer 0
    {
        int gn = min(kln, NTOK - 1);
        const float* ksrc = kb + (size_t)gn * HD + klp;
        const float* vsrc = vtb + (size_t)vrow * VTSTR + vseg;
        cp16(ksm[0], ksrc);          cp16(ksm[0] + 16, ksrc + 4);
        cp16(ksm[0] + 32, ksrc + 8); cp16(ksm[0] + 48, ksrc + 12);
        cp16(vsm[0], vsrc);          cp16(vsm[0] + 16, vsrc + 4);
        cp16(vsm[0] + 32, vsrc + 8); cp16(vsm[0] + 48, vsrc + 12);
        cp_commit();
    }
    cp_wait0();
    __syncthreads();

    for (int c = 0; c < 6; c++) {
        const int buf = c & 1;
        if (c < 5) {
            int gn = min((c + 1) * 64 + kln, NTOK - 1);
            const float* ksrc = kb + (size_t)gn * HD + klp;
            const float* vsrc = vtb + (size_t)vrow * VTSTR + (c + 1) * 64 + vseg;
            const int nb = buf ^ 1;
            cp16(ksm[nb], ksrc);          cp16(ksm[nb] + 16, ksrc + 4);
            cp16(ksm[nb] + 32, ksrc + 8); cp16(ksm[nb] + 48, ksrc + 12);
            cp16(vsm[nb], vsrc);          cp16(vsm[nb] + 16, vsrc + 4);
            cp16(vsm[nb] + 32, vsrc + 8); cp16(vsm[nb] + 48, vsrc + 12);
            cp_commit();
        }
        const float* Ks = KsA[buf];
        const float* Vs = VsA[buf];

#pragma unroll
        for (int h32 = 0; h32 < 2; h32++) {
            const int kb0 = c * 64 + h32 * 32;
            if (kb0 >= NTOK) continue;   // fully-masked subchunk contributes 0
            const int nrow0 = h32 * 32;

            // S = Q K^T : 4 n-frags x 4 k-steps x 2 M-tiles; B-frag shared
            float sacc[2][4][4];
#pragma unroll
            for (int mt = 0; mt < 2; mt++)
#pragma unroll
                for (int nf = 0; nf < 4; nf++)
#pragma unroll
                    for (int r = 0; r < 4; r++) sacc[mt][nf][r] = 0.f;
#pragma unroll
            for (int ks = 0; ks < 4; ks++) {
#pragma unroll
                for (int nf = 0; nf < 4; nf++) {
                    float2 bp = *(const float2*)&Ks[(nrow0 + nf * 8 + g) * KSTR + ks * 8 + 2 * t];
                    uint32_t b0 = __float_as_uint(bp.x), b1 = __float_as_uint(bp.y);
                    mma_tf32(sacc[0][nf][0], sacc[0][nf][1], sacc[0][nf][2], sacc[0][nf][3],
                             qa[0][ks][0], qa[0][ks][1], qa[0][ks][2], qa[0][ks][3], b0, b1);
                    mma_tf32(sacc[1][nf][0], sacc[1][nf][1], sacc[1][nf][2], sacc[1][nf][3],
                             qa[1][ks][0], qa[1][ks][1], qa[1][ks][2], qa[1][ks][3], b0, b1);
                }
            }

            // + bias + mask, OOB -> -inf, subchunk row max (4 row groups)
            float cm[4] = {-1e30f, -1e30f, -1e30f, -1e30f};
#pragma unroll
            for (int nf = 0; nf < 4; nf++) {
                int col = kb0 + nf * 8 + 2 * t;
                bool in0 = (col < NTOK), in1 = (col + 1 < NTOK);
#pragma unroll
                for (int j = 0; j < 4; j++) {
                    float2 bv = *(const float2*)(bbase + boff[j] + col);
                    float2 mv = *(const float2*)(mbase + boff[j] + col);
                    float& s0 = sacc[j >> 1][nf][(j & 1) * 2 + 0];
                    float& s1 = sacc[j >> 1][nf][(j & 1) * 2 + 1];
                    s0 = in0 ? s0 + bv.x + mv.x : -1e30f;
                    s1 = in1 ? s1 + bv.y + mv.y : -1e30f;
                    cm[j] = fmaxf(cm[j], fmaxf(s0, s1));
                }
            }
#pragma unroll
            for (int j = 0; j < 4; j++) {
                cm[j] = fmaxf(cm[j], __shfl_xor_sync(0xffffffffu, cm[j], 1));
                cm[j] = fmaxf(cm[j], __shfl_xor_sync(0xffffffffu, cm[j], 2));
            }

            float mn[4], sc[4];
#pragma unroll
            for (int j = 0; j < 4; j++) {
                mn[j] = fmaxf(rm[j], cm[j]);
                sc[j] = __expf(rm[j] - mn[j]);
                rm[j] = mn[j];
            }

            // exp in-place; P stays in registers as PV A-fragments
            float ls[4] = {0.f, 0.f, 0.f, 0.f};
#pragma unroll
            for (int nf = 0; nf < 4; nf++) {
#pragma unroll
                for (int j = 0; j < 4; j++) {
                    float& s0 = sacc[j >> 1][nf][(j & 1) * 2 + 0];
                    float& s1 = sacc[j >> 1][nf][(j & 1) * 2 + 1];
                    float p0 = __expf(s0 - mn[j]);
                    float p1 = __expf(s1 - mn[j]);
                    ls[j] += p0 + p1;
                    s0 = to_tf32(p0);
                    s1 = to_tf32(p1);
                }
            }
#pragma unroll
            for (int j = 0; j < 4; j++) {
                ls[j] += __shfl_xor_sync(0xffffffffu, ls[j], 1);
                ls[j] += __shfl_xor_sync(0xffffffffu, ls[j], 2);
                l[j] = l[j] * sc[j] + ls[j];
            }

#pragma unroll
            for (int mt = 0; mt < 2; mt++)
#pragma unroll
                for (int df = 0; df < 4; df++) {
                    oacc[mt][df][0] *= sc[2 * mt];
                    oacc[mt][df][1] *= sc[2 * mt];
                    oacc[mt][df][2] *= sc[2 * mt + 1];
                    oacc[mt][df][3] *= sc[2 * mt + 1];
                }

            // O += P V : A-frags direct from sacc; V B-frag shared by 2 M-tiles
#pragma unroll
            for (int ks = 0; ks < 4; ks++) {
                uint32_t aA0 = __float_as_uint(sacc[0][ks][0]);
                uint32_t aA1 = __float_as_uint(sacc[0][ks][2]);
                uint32_t aA2 = __float_as_uint(sacc[0][ks][1]);
                uint32_t aA3 = __float_as_uint(sacc[0][ks][3]);
                uint32_t aB0 = __float_as_uint(sacc[1][ks][0]);
                uint32_t aB1 = __float_as_uint(sacc[1][ks][2]);
                uint32_t aB2 = __float_as_uint(sacc[1][ks][1]);
                uint32_t aB3 = __float_as_uint(sacc[1][ks][3]);
#pragma unroll
                for (int df = 0; df < 4; df++) {
                    float2 vv = *(const float2*)&Vs[(df * 8 + g) * VSTR + nrow0 + ks * 8 + 2 * t];
                    uint32_t b0 = __float_as_uint(vv.x), b1 = __float_as_uint(vv.y);
                    mma_tf32(oacc[0][df][0], oacc[0][df][1], oacc[0][df][2], oacc[0][df][3],
                             aA0, aA1, aA2, aA3, b0, b1);
                    mma_tf32(oacc[1][df][0], oacc[1][df][1], oacc[1][df][2], oacc[1][df][3],
                             aB0, aB1, aB2, aB3, b0, b1);
                }
            }
        }

        if (c < 5) cp_wait0();
        __syncthreads();
    }

    // epilogue: normalize + store (4 row groups)
#pragma unroll
    for (int j = 0; j < 4; j++) {
        if (rr[j] < NTOK) {
            float inv = 1.f / l[j];
            float* orow = g_o + ((size_t)bb * NTOK + rr[j]) * CDIM + h * HD;
            const int mt = j >> 1, rb = (j & 1) * 2;
#pragma unroll
            for (int df = 0; df < 4; df++)
                *(float2*)(orow + df * 8 + 2 * t) =
                    make_float2(oacc[mt][df][rb] * inv, oacc[mt][df][rb + 1] * inv);
        }
    }
}

// ---------------------------------------------------------------------------
// Launch
// ---------------------------------------------------------------------------
extern "C" void kernel_launch(void* const* d_in, const int* in_sizes, int n_in,
                              void* d_out, int out_size) {
    const float* x      = (const float*)d_in[0];
    // d_in[1..3] = D,H,W scalars (constant 7) — unused
    const float* mask   = (const float*)d_in[4];
    const float* qg     = (const float*)d_in[5];
    const float* kv_w   = (const float*)d_in[6];
    const float* proj_w = (const float*)d_in[7];
    const float* proj_b = (const float*)d_in[8];
    const float* rpb    = (const float*)d_in[9];
    float* out = (float*)d_out;

    cudaFuncSetAttribute(attn_mma, cudaFuncAttributeMaxDynamicSharedMemorySize, ATT_SMEM);

    // 1) padded bias + mask tables
    bias_kernel<<<(NTOK * BMSTR + 255) / 256, 256>>>(rpb);
    mask_copy_kernel<<<(64 * NTOK * BMSTR + 255) / 256, 256>>>(mask);

    // 2) KV projection: [43904,512] x [1024,512]^T -> g_k (perm) / g_vT (transposed)
    gemm_tf32<<<dim3(1024 / 128, MROWS / 128), 256>>>(x, kv_w, nullptr, nullptr, 0);

    // 3) tensor-core flash attention -> g_o
    attn_mma<<<dim3(NB * NH, 3), 128, ATT_SMEM>>>(qg);

    // 4) output projection: [43904,512] x [512,512]^T + bias -> d_out (tf32 MMA)
    gemm_tf32<<<dim3(CDIM / 128, MROWS / 128), 256>>>(nullptr, proj_w, out, proj_b, 1);
}

// round 15
// speedup vs baseline: 1.2593x; 1.2593x over previous
#include <cuda_runtime.h>
#include <cstdint>

// ---------------------------------------------------------------------------
// Problem constants
// ---------------------------------------------------------------------------
#define NB     128          // b = B*nw
#define NTOK   343          // n
#define CDIM   512          // c
#define NH     16           // heads
#define HD     32           // head dim
#define MROWS  (NB * NTOK)  // 43904 = 343 * 128
#define SCALE_F 0.17677669529663687f   // 32^-0.5
#define BMSTR  384          // padded bias/mask row stride (covers col<=383 reads)
#define VTSTR  384          // padded V^T row stride (keys), 16B-aligned rows

// ---------------------------------------------------------------------------
// Scratch (device globals; no allocations allowed)
// ---------------------------------------------------------------------------
__device__ float g_k[(size_t)NB * NH * NTOK * HD];        // [b][h][n][32] d-permuted, tf32
__device__ float g_vT[(size_t)NB * NH * HD * VTSTR];      // [b][h][d][n] transposed, tf32
__device__ float g_bias[(size_t)NH * NTOK * BMSTR];       // [h][i][j] stride 384
__device__ float g_maskp[(size_t)64 * NTOK * BMSTR];      // [wi][i][j] stride 384
__device__ float g_o[(size_t)MROWS * CDIM];               // [b*n][c] head-major cols

// ---------------------------------------------------------------------------
// Kernel 1a: relative position bias  bias[h][i][j] = rpb[rel(i,j)*16 + h]
// ---------------------------------------------------------------------------
__global__ void bias_kernel(const float* __restrict__ rpb) {
    int idx = blockIdx.x * 256 + threadIdx.x;
    if (idx >= NTOK * BMSTR) return;
    int i = idx / BMSTR, j = idx % BMSTR;
    if (j >= NTOK) {
#pragma unroll
        for (int h = 0; h < NH; h++)
            g_bias[(size_t)h * NTOK * BMSTR + idx] = 0.f;
        return;
    }
    int di = i / 49, hi = (i / 7) % 7, wi = i % 7;
    int dj = j / 49, hj = (j / 7) % 7, wj = j % 7;
    int rel = (di - dj + 6) * 169 + (hi - hj + 6) * 13 + (wi - wj + 6);
    const float* src = rpb + rel * NH;
#pragma unroll
    for (int h = 0; h < NH; h++)
        g_bias[(size_t)h * NTOK * BMSTR + idx] = src[h];
}

// ---------------------------------------------------------------------------
// Kernel 1b: repack mask into padded stride-384 table
// ---------------------------------------------------------------------------
__global__ void mask_copy_kernel(const float* __restrict__ mask) {
    int idx = blockIdx.x * 256 + threadIdx.x;
    if (idx >= 64 * NTOK * BMSTR) return;
    int w = idx / (NTOK * BMSTR);
    int r = idx % (NTOK * BMSTR);
    int i = r / BMSTR, j = r % BMSTR;
    g_maskp[idx] = (j < NTOK) ? mask[((size_t)w * NTOK + i) * NTOK + j] : 0.f;
}

// ---------------------------------------------------------------------------
// tf32 / cp.async helpers
// ---------------------------------------------------------------------------
__device__ __forceinline__ float to_tf32(float x) {
    asm("cvt.rna.tf32.f32 %0, %0;" : "+f"(x));
    return x;
}

__device__ __forceinline__ void mma_tf32(float& d0, float& d1, float& d2, float& d3,
                                         uint32_t a0, uint32_t a1, uint32_t a2, uint32_t a3,
                                         uint32_t b0, uint32_t b1) {
    asm volatile(
        "mma.sync.aligned.m16n8k8.row.col.f32.tf32.tf32.f32 "
        "{%0,%1,%2,%3},{%4,%5,%6,%7},{%8,%9},{%0,%1,%2,%3};"
        : "+f"(d0), "+f"(d1), "+f"(d2), "+f"(d3)
        : "r"(a0), "r"(a1), "r"(a2), "r"(a3), "r"(b0), "r"(b1));
}

__device__ __forceinline__ void cp16(uint32_t dst, const void* src) {
    asm volatile("cp.async.cg.shared.global [%0], [%1], 16;" :: "r"(dst), "l"(src));
}
__device__ __forceinline__ void cp_commit() {
    asm volatile("cp.async.commit_group;");
}
__device__ __forceinline__ void cp_wait0() {
    asm volatile("cp.async.wait_group 0;");
}

// within-8-group column permutation so B-frag pairs (t, t+4) sit adjacent
__device__ __forceinline__ int dperm(int d) {
    return (d & 24) | ((d & 3) << 1) | ((d >> 2) & 1);
}

// ---------------------------------------------------------------------------
// Kernel 2/4: tf32 tensor-core GEMM  C[M,N] = A[M,K] * B[N,K]^T
// mode 0 epilogue: K -> g_k (d-permuted), V -> g_vT (transposed), tf32-rounded
// mode 1 epilogue: Cout = acc + cbias, A = g_o
// ---------------------------------------------------------------------------
#define GSTR 136

__global__ __launch_bounds__(256, 2)
void gemm_tf32(const float* __restrict__ Ain,
               const float* __restrict__ Bw,
               float* __restrict__ Cout,
               const float* __restrict__ cbias,
               int mode) {
    const float* A = (mode == 1) ? g_o : Ain;

    __shared__ float As[2][16][GSTR];
    __shared__ float Bs[2][16][GSTR];

    const int tid  = threadIdx.x;
    const int warp = tid >> 5;
    const int lane = tid & 31;
    const int qr   = lane >> 2;   // 0..7
    const int qk   = lane & 3;    // 0..3
    const int warpM = (warp & 1) * 64;
    const int warpN = (warp >> 1) * 32;

    const int rowBase = blockIdx.y * 128;
    const int colBase = blockIdx.x * 128;

    const int m0 = tid >> 2;
    const int kq = tid & 3;
    const float* a0p = A  + (size_t)(rowBase + m0) * CDIM + kq * 4;
    const float* a1p = a0p + (size_t)64 * CDIM;
    const float* b0p = Bw + (size_t)(colBase + m0) * CDIM + kq * 4;
    const float* b1p = b0p + (size_t)64 * CDIM;
    const int swS = kq << 3;

    float acc[4][4][4];
#pragma unroll
    for (int mt = 0; mt < 4; mt++)
#pragma unroll
        for (int nt = 0; nt < 4; nt++)
#pragma unroll
            for (int r = 0; r < 4; r++) acc[mt][nt][r] = 0.f;

    float4 ra0, ra1, rb0, rb1;

    ra0 = *(const float4*)(a0p); ra1 = *(const float4*)(a1p);
    rb0 = *(const float4*)(b0p); rb1 = *(const float4*)(b1p);
    {
        float av0[4] = {ra0.x, ra0.y, ra0.z, ra0.w};
        float av1[4] = {ra1.x, ra1.y, ra1.z, ra1.w};
        float bv0[4] = {rb0.x, rb0.y, rb0.z, rb0.w};
        float bv1[4] = {rb1.x, rb1.y, rb1.z, rb1.w};
#pragma unroll
        for (int j = 0; j < 4; j++) {
            As[0][kq * 4 + j][m0 ^ swS]        = to_tf32(av0[j]);
            As[0][kq * 4 + j][(m0 + 64) ^ swS] = to_tf32(av1[j]);
            Bs[0][kq * 4 + j][m0 ^ swS]        = to_tf32(bv0[j]);
            Bs[0][kq * 4 + j][(m0 + 64) ^ swS] = to_tf32(bv1[j]);
        }
    }
    __syncthreads();

    for (int it = 0; it < 32; ++it) {
        const int buf = it & 1;
        if (it < 31) {
            const int off = (it + 1) * 16;
            ra0 = *(const float4*)(a0p + off); ra1 = *(const float4*)(a1p + off);
            rb0 = *(const float4*)(b0p + off); rb1 = *(const float4*)(b1p + off);
        }

#pragma unroll
        for (int ks = 0; ks < 16; ks += 8) {
            uint32_t af[4][4], bf[4][2];
            const int kA = ks + qk;
            const int kB = ks + qk + 4;
            const int sA = ((kA >> 2) << 3);
            const int sB = ((kB >> 2) << 3);
#pragma unroll
            for (int mt = 0; mt < 4; mt++) {
                const int m = warpM + mt * 16 + qr;
                af[mt][0] = __float_as_uint(As[buf][kA][m ^ sA]);
                af[mt][1] = __float_as_uint(As[buf][kA][(m + 8) ^ sA]);
                af[mt][2] = __float_as_uint(As[buf][kB][m ^ sB]);
                af[mt][3] = __float_as_uint(As[buf][kB][(m + 8) ^ sB]);
            }
#pragma unroll
            for (int nt = 0; nt < 4; nt++) {
                const int nn = warpN + nt * 8 + qr;
                bf[nt][0] = __float_as_uint(Bs[buf][kA][nn ^ sA]);
                bf[nt][1] = __float_as_uint(Bs[buf][kB][nn ^ sB]);
            }
#pragma unroll
            for (int mt = 0; mt < 4; mt++)
#pragma unroll
                for (int nt = 0; nt < 4; nt++)
                    mma_tf32(acc[mt][nt][0], acc[mt][nt][1], acc[mt][nt][2], acc[mt][nt][3],
                             af[mt][0], af[mt][1], af[mt][2], af[mt][3],
                             bf[nt][0], bf[nt][1]);
        }

        if (it < 31) {
            const int nbuf = buf ^ 1;
            float av0[4] = {ra0.x, ra0.y, ra0.z, ra0.w};
            float av1[4] = {ra1.x, ra1.y, ra1.z, ra1.w};
            float bv0[4] = {rb0.x, rb0.y, rb0.z, rb0.w};
            float bv1[4] = {rb1.x, rb1.y, rb1.z, rb1.w};
#pragma unroll
            for (int j = 0; j < 4; j++) {
                As[nbuf][kq * 4 + j][m0 ^ swS]        = to_tf32(av0[j]);
                As[nbuf][kq * 4 + j][(m0 + 64) ^ swS] = to_tf32(av1[j]);
                Bs[nbuf][kq * 4 + j][m0 ^ swS]        = to_tf32(bv0[j]);
                Bs[nbuf][kq * 4 + j][(m0 + 64) ^ swS] = to_tf32(bv1[j]);
            }
        }
        __syncthreads();
    }

    if (mode == 0) {
        // K -> g_k (d-permuted within 8-groups); V -> g_vT (transposed). tf32-rounded.
#pragma unroll
        for (int mt = 0; mt < 4; mt++) {
            const int row = rowBase + warpM + mt * 16 + qr;
            const int bb0 = row / NTOK;
            const int nn0 = row - bb0 * NTOK;
            const int bb8 = (row + 8) / NTOK;
            const int nn8 = (row + 8) - bb8 * NTOK;
#pragma unroll
            for (int nt = 0; nt < 4; nt++) {
                const int col = colBase + warpN + nt * 8 + qk * 2;
                const int d   = col & 31;
                const float v0 = to_tf32(acc[mt][nt][0]);
                const float v1 = to_tf32(acc[mt][nt][1]);
                const float v2 = to_tf32(acc[mt][nt][2]);
                const float v3 = to_tf32(acc[mt][nt][3]);
                if (col < 512) {
                    const int hv = col >> 5;
                    const int d0p = dperm(d), d1p = dperm(d + 1);
                    size_t base0 = ((((size_t)bb0 * NH + hv) * NTOK) + nn0) * HD;
                    size_t base8 = ((((size_t)bb8 * NH + hv) * NTOK) + nn8) * HD;
                    g_k[base0 + d0p] = v0;  g_k[base0 + d1p] = v1;
                    g_k[base8 + d0p] = v2;  g_k[base8 + d1p] = v3;
                } else {
                    const int hv = (col - 512) >> 5;
                    size_t r0v = (((size_t)bb0 * NH + hv) * HD + d) * VTSTR;
                    size_t r1v = (((size_t)bb0 * NH + hv) * HD + d + 1) * VTSTR;
                    size_t r0w = (((size_t)bb8 * NH + hv) * HD + d) * VTSTR;
                    size_t r1w = (((size_t)bb8 * NH + hv) * HD + d + 1) * VTSTR;
                    g_vT[r0v + nn0] = v0;  g_vT[r1v + nn0] = v1;
                    g_vT[r0w + nn8] = v2;  g_vT[r1w + nn8] = v3;
                }
            }
        }
    } else {
#pragma unroll
        for (int mt = 0; mt < 4; mt++) {
            const int row = rowBase + warpM + mt * 16 + qr;
#pragma unroll
            for (int nt = 0; nt < 4; nt++) {
                const int col = colBase + warpN + nt * 8 + qk * 2;
                const float b0v = cbias[col], b1v = cbias[col + 1];
                *(float2*)(Cout + (size_t)row * CDIM + col) =
                    make_float2(acc[mt][nt][0] + b0v, acc[mt][nt][1] + b1v);
                *(float2*)(Cout + (size_t)(row + 8) * CDIM + col) =
                    make_float2(acc[mt][nt][2] + b0v, acc[mt][nt][3] + b1v);
            }
        }
    }
}

// ---------------------------------------------------------------------------
// Kernel 3: tensor-core flash attention, cp.async double-buffered.
// grid (b*h = 2048, 3 query tiles of 128), block 256 (8 warps, 16 q/warp).
// P never touches smem: S C-frags feed PV A-frags directly; K/V B-frags are
// single float2 LDS. Fully-OOB subchunk (kb0 >= 343) skipped (exact).
// smem: K 2*[64][40] + V^T 2*[32][72] = 38912 B
// ---------------------------------------------------------------------------
#define KSTR 40
#define VSTR 72
#define ATT_SMEM ((2 * 64 * KSTR + 2 * 32 * VSTR) * 4)

__global__ __launch_bounds__(256, 3)
void attn_mma(const float* __restrict__ qg) {
    const int bh = blockIdx.x;
    const int bb = bh >> 4, h = bh & 15;
    const int Bi = bb >> 6, wi = bb & 63;
    const int qbase = blockIdx.y * 128;
    const int tid = threadIdx.x, warp = tid >> 5, lane = tid & 31;
    const int g = lane >> 2, t = lane & 3;

    extern __shared__ float sm[];
    float* KsA[2] = {sm, sm + 64 * KSTR};
    float* VsA[2] = {sm + 2 * 64 * KSTR, sm + 2 * 64 * KSTR + 32 * VSTR};

    const int r0 = qbase + warp * 16 + g;
    const int r1 = r0 + 8;
    const int r0c = min(r0, NTOK - 1), r1c = min(r1, NTOK - 1);

    // Q fragments (registers, pre-scaled). Natural d order (K permutation
    // was chosen so Q fragment indexing is unchanged).
    const float* q0p = qg + (((size_t)Bi * NH + h) * NTOK + r0c) * HD;
    const float* q1p = qg + (((size_t)Bi * NH + h) * NTOK + r1c) * HD;
    uint32_t qa[4][4];
#pragma unroll
    for (int ks = 0; ks < 4; ks++) {
        qa[ks][0] = __float_as_uint(to_tf32(q0p[ks * 8 + t] * SCALE_F));
        qa[ks][1] = __float_as_uint(to_tf32(q1p[ks * 8 + t] * SCALE_F));
        qa[ks][2] = __float_as_uint(to_tf32(q0p[ks * 8 + t + 4] * SCALE_F));
        qa[ks][3] = __float_as_uint(to_tf32(q1p[ks * 8 + t + 4] * SCALE_F));
    }

    const float* brow0 = g_bias  + ((size_t)h  * NTOK + r0c) * BMSTR;
    const float* brow1 = g_bias  + ((size_t)h  * NTOK + r1c) * BMSTR;
    const float* mrow0 = g_maskp + ((size_t)wi * NTOK + r0c) * BMSTR;
    const float* mrow1 = g_maskp + ((size_t)wi * NTOK + r1c) * BMSTR;

    const float* kb  = g_k  + ((size_t)bb * NH + h) * NTOK * HD;
    const float* vtb = g_vT + ((size_t)bb * NH + h) * HD * VTSTR;

    // staging: K = 64 rows x 32 floats; V^T = 32 rows x 64 floats
    const int kln = tid >> 2, klp = (tid & 3) * 8;
    const int vrow = tid >> 3, vseg = (tid & 7) * 8;

    const uint32_t ksm[2] = {(uint32_t)__cvta_generic_to_shared(KsA[0] + kln * KSTR + klp),
                             (uint32_t)__cvta_generic_to_shared(KsA[1] + kln * KSTR + klp)};
    const uint32_t vsm[2] = {(uint32_t)__cvta_generic_to_shared(VsA[0] + vrow * VSTR + vseg),
                             (uint32_t)__cvta_generic_to_shared(VsA[1] + vrow * VSTR + vseg)};

    float rm0 = -1e30f, rm1 = -1e30f, l0 = 0.f, l1 = 0.f;
    float oacc[4][4];
#pragma unroll
    for (int df = 0; df < 4; df++)
#pragma unroll
        for (int r = 0; r < 4; r++) oacc[df][r] = 0.f;

    // prologue: stage chunk 0 into buffer 0
    {
        int gn = min(kln, NTOK - 1);
        const float* ksrc = kb + (size_t)gn * HD + klp;
        const float* vsrc = vtb + (size_t)vrow * VTSTR + vseg;
        cp16(ksm[0], ksrc);     cp16(ksm[0] + 16, ksrc + 4);
        cp16(vsm[0], vsrc);     cp16(vsm[0] + 16, vsrc + 4);
        cp_commit();
    }
    cp_wait0();
    __syncthreads();

    for (int c = 0; c < 6; c++) {
        const int buf = c & 1;
        if (c < 5) {
            int gn = min((c + 1) * 64 + kln, NTOK - 1);
            const float* ksrc = kb + (size_t)gn * HD + klp;
            const float* vsrc = vtb + (size_t)vrow * VTSTR + (c + 1) * 64 + vseg;
            const int nb = buf ^ 1;
            cp16(ksm[nb], ksrc);     cp16(ksm[nb] + 16, ksrc + 4);
            cp16(vsm[nb], vsrc);     cp16(vsm[nb] + 16, vsrc + 4);
            cp_commit();
        }
        const float* Ks = KsA[buf];
        const float* Vs = VsA[buf];

#pragma unroll
        for (int h32 = 0; h32 < 2; h32++) {
            const int kb0 = c * 64 + h32 * 32;
            if (kb0 >= NTOK) break;      // fully-masked subchunk contributes exactly 0
            const int nrow0 = h32 * 32;

            // S = Q K^T : 4 n-frags x 4 k-steps; B-frag = one float2 LDS
            float sacc[4][4];
#pragma unroll
            for (int nf = 0; nf < 4; nf++)
#pragma unroll
                for (int r = 0; r < 4; r++) sacc[nf][r] = 0.f;
#pragma unroll
            for (int ks = 0; ks < 4; ks++) {
#pragma unroll
                for (int nf = 0; nf < 4; nf++) {
                    float2 bp = *(const float2*)&Ks[(nrow0 + nf * 8 + g) * KSTR + ks * 8 + 2 * t];
                    mma_tf32(sacc[nf][0], sacc[nf][1], sacc[nf][2], sacc[nf][3],
                             qa[ks][0], qa[ks][1], qa[ks][2], qa[ks][3],
                             __float_as_uint(bp.x), __float_as_uint(bp.y));
                }
            }

            // + bias + mask, OOB -> -inf, subchunk row max
            float cm0 = -1e30f, cm1 = -1e30f;
#pragma unroll
            for (int nf = 0; nf < 4; nf++) {
                int col = kb0 + nf * 8 + 2 * t;
                float2 bv0 = *(const float2*)(brow0 + col);
                float2 mv0 = *(const float2*)(mrow0 + col);
                float2 bv1 = *(const float2*)(brow1 + col);
                float2 mv1 = *(const float2*)(mrow1 + col);
                sacc[nf][0] = (col     < NTOK) ? sacc[nf][0] + bv0.x + mv0.x : -1e30f;
                sacc[nf][1] = (col + 1 < NTOK) ? sacc[nf][1] + bv0.y + mv0.y : -1e30f;
                sacc[nf][2] = (col     < NTOK) ? sacc[nf][2] + bv1.x + mv1.x : -1e30f;
                sacc[nf][3] = (col + 1 < NTOK) ? sacc[nf][3] + bv1.y + mv1.y : -1e30f;
                cm0 = fmaxf(cm0, fmaxf(sacc[nf][0], sacc[nf][1]));
                cm1 = fmaxf(cm1, fmaxf(sacc[nf][2], sacc[nf][3]));
            }
            cm0 = fmaxf(cm0, __shfl_xor_sync(0xffffffffu, cm0, 1));
            cm0 = fmaxf(cm0, __shfl_xor_sync(0xffffffffu, cm0, 2));
            cm1 = fmaxf(cm1, __shfl_xor_sync(0xffffffffu, cm1, 1));
            cm1 = fmaxf(cm1, __shfl_xor_sync(0xffffffffu, cm1, 2));

            float mn0 = fmaxf(rm0, cm0), mn1 = fmaxf(rm1, cm1);
            float sc0 = __expf(rm0 - mn0), sc1 = __expf(rm1 - mn1);
            rm0 = mn0; rm1 = mn1;

            // exp in-place; P stays in registers as PV A-fragments
            float ls0 = 0.f, ls1 = 0.f;
#pragma unroll
            for (int nf = 0; nf < 4; nf++) {
                float p0 = __expf(sacc[nf][0] - mn0);
                float p1 = __expf(sacc[nf][1] - mn0);
                float p2 = __expf(sacc[nf][2] - mn1);
                float p3 = __expf(sacc[nf][3] - mn1);
                ls0 += p0 + p1; ls1 += p2 + p3;
                sacc[nf][0] = to_tf32(p0);
                sacc[nf][1] = to_tf32(p1);
                sacc[nf][2] = to_tf32(p2);
                sacc[nf][3] = to_tf32(p3);
            }
            ls0 += __shfl_xor_sync(0xffffffffu, ls0, 1);
            ls0 += __shfl_xor_sync(0xffffffffu, ls0, 2);
            ls1 += __shfl_xor_sync(0xffffffffu, ls1, 1);
            ls1 += __shfl_xor_sync(0xffffffffu, ls1, 2);
            l0 = l0 * sc0 + ls0;
            l1 = l1 * sc1 + ls1;

#pragma unroll
            for (int df = 0; df < 4; df++) {
                oacc[df][0] *= sc0; oacc[df][1] *= sc0;
                oacc[df][2] *= sc1; oacc[df][3] *= sc1;
            }

            // O += P V : A-frags direct from sacc regs; B-frag = one float2 LDS
#pragma unroll
            for (int ks = 0; ks < 4; ks++) {
                uint32_t a0 = __float_as_uint(sacc[ks][0]);
                uint32_t a1 = __float_as_uint(sacc[ks][2]);
                uint32_t a2 = __float_as_uint(sacc[ks][1]);
                uint32_t a3 = __float_as_uint(sacc[ks][3]);
#pragma unroll
                for (int df = 0; df < 4; df++) {
                    float2 vv = *(const float2*)&Vs[(df * 8 + g) * VSTR + nrow0 + ks * 8 + 2 * t];
                    mma_tf32(oacc[df][0], oacc[df][1], oacc[df][2], oacc[df][3],
                             a0, a1, a2, a3,
                             __float_as_uint(vv.x), __float_as_uint(vv.y));
                }
            }
        }

        if (c < 5) cp_wait0();
        __syncthreads();
    }

    // epilogue: normalize + store
    float inv0 = 1.f / l0, inv1 = 1.f / l1;
    if (r0 < NTOK) {
        float* orow = g_o + ((size_t)bb * NTOK + r0) * CDIM + h * HD;
#pragma unroll
        for (int df = 0; df < 4; df++)
            *(float2*)(orow + df * 8 + 2 * t) =
                make_float2(oacc[df][0] * inv0, oacc[df][1] * inv0);
    }
    if (r1 < NTOK) {
        float* orow = g_o + ((size_t)bb * NTOK + r1) * CDIM + h * HD;
#pragma unroll
        for (int df = 0; df < 4; df++)
            *(float2*)(orow + df * 8 + 2 * t) =
                make_float2(oacc[df][2] * inv1, oacc[df][3] * inv1);
    }
}

// ---------------------------------------------------------------------------
// Launch
// ---------------------------------------------------------------------------
extern "C" void kernel_launch(void* const* d_in, const int* in_sizes, int n_in,
                              void* d_out, int out_size) {
    const float* x      = (const float*)d_in[0];
    // d_in[1..3] = D,H,W scalars (constant 7) — unused
    const float* mask   = (const float*)d_in[4];
    const float* qg     = (const float*)d_in[5];
    const float* kv_w   = (const float*)d_in[6];
    const float* proj_w = (const float*)d_in[7];
    const float* proj_b = (const float*)d_in[8];
    const float* rpb    = (const float*)d_in[9];
    float* out = (float*)d_out;

    cudaFuncSetAttribute(attn_mma, cudaFuncAttributeMaxDynamicSharedMemorySize, ATT_SMEM);

    // 1) padded bias + mask tables
    bias_kernel<<<(NTOK * BMSTR + 255) / 256, 256>>>(rpb);
    mask_copy_kernel<<<(64 * NTOK * BMSTR + 255) / 256, 256>>>(mask);

    // 2) KV projection: [43904,512] x [1024,512]^T -> g_k (perm) / g_vT (transposed)
    gemm_tf32<<<dim3(1024 / 128, MROWS / 128), 256>>>(x, kv_w, nullptr, nullptr, 0);

    // 3) tensor-core flash attention -> g_o
    attn_mma<<<dim3(NB * NH, 3), 256, ATT_SMEM>>>(qg);

    // 4) output projection: [43904,512] x [512,512]^T + bias -> d_out (tf32 MMA)
    gemm_tf32<<<dim3(CDIM / 128, MROWS / 128), 256>>>(nullptr, proj_w, out, proj_b, 1);
}

// round 17
// speedup vs baseline: 1.3717x; 1.0892x over previous
#include <cuda_runtime.h>
#include <cstdint>

// ---------------------------------------------------------------------------
// Problem constants
// ---------------------------------------------------------------------------
#define NB     128          // b = B*nw
#define NTOK   343          // n
#define CDIM   512          // c
#define NH     16           // heads
#define HD     32           // head dim
#define MROWS  (NB * NTOK)  // 43904 = 343 * 128
#define SCALE_F 0.17677669529663687f   // 32^-0.5
#define BMSTR  384          // padded bias/mask row stride
#define VTSTR  384          // padded V^T row stride (keys)

// ---------------------------------------------------------------------------
// Scratch (device globals; no allocations allowed)
// ---------------------------------------------------------------------------
__device__ float g_k[(size_t)NB * NH * NTOK * HD];    // [b][h][n][32] k-packed, tf32
__device__ float g_vT[(size_t)NB * NH * HD * VTSTR];  // [b][h][d][keys] key-permuted, tf32-ish
__device__ float g_bias[(size_t)NH * NTOK * BMSTR];   // [h][i][j'] col-permuted
__device__ float g_maskp[(size_t)64 * NTOK * BMSTR];  // [wi][i][j'] col-permuted
__device__ float g_o[(size_t)MROWS * CDIM];           // [b*n][c] head-major cols

// Permutations (involutions within 32-element blocks):
//   perm32: j = 8k+2t+b  ->  8t+2k+b   (bias/mask cols, V^T keys)
//   kperm : d = 8k+t+4u  ->  8t+2k+u   (K head-dim)
__host__ __device__ __forceinline__ int perm32(int x) {
    return ((x & 6) << 2) | ((x & 24) >> 2) | (x & 1);
}
__device__ __forceinline__ int kperm(int d) {
    return ((d & 3) << 3) | ((d & 24) >> 2) | ((d & 4) >> 2);
}

// ---------------------------------------------------------------------------
// Kernel 1a: relative position bias  bias[h][i][j'] = rpb[rel(i,j)*16 + h]
// with j = blockwise perm32(j')
// ---------------------------------------------------------------------------
__global__ void bias_kernel(const float* __restrict__ rpb) {
    int idx = blockIdx.x * 256 + threadIdx.x;
    if (idx >= NTOK * BMSTR) return;
    int i = idx / BMSTR, js = idx % BMSTR;
    int j = (js & ~31) | perm32(js & 31);
    if (j >= NTOK) {
#pragma unroll
        for (int h = 0; h < NH; h++)
            g_bias[(size_t)h * NTOK * BMSTR + idx] = 0.f;
        return;
    }
    int di = i / 49, hi = (i / 7) % 7, wi = i % 7;
    int dj = j / 49, hj = (j / 7) % 7, wj = j % 7;
    int rel = (di - dj + 6) * 169 + (hi - hj + 6) * 13 + (wi - wj + 6);
    const float* src = rpb + rel * NH;
#pragma unroll
    for (int h = 0; h < NH; h++)
        g_bias[(size_t)h * NTOK * BMSTR + idx] = src[h];
}

// ---------------------------------------------------------------------------
// Kernel 1b: repack mask into padded col-permuted table
// ---------------------------------------------------------------------------
__global__ void mask_copy_kernel(const float* __restrict__ mask) {
    int idx = blockIdx.x * 256 + threadIdx.x;
    if (idx >= 64 * NTOK * BMSTR) return;
    int w = idx / (NTOK * BMSTR);
    int r = idx % (NTOK * BMSTR);
    int i = r / BMSTR, js = r % BMSTR;
    int j = (js & ~31) | perm32(js & 31);
    g_maskp[idx] = (j < NTOK) ? mask[((size_t)w * NTOK + i) * NTOK + j] : 0.f;
}

// ---------------------------------------------------------------------------
// tf32 / cp.async helpers
// ---------------------------------------------------------------------------
__device__ __forceinline__ float to_tf32(float x) {
    asm("cvt.rna.tf32.f32 %0, %0;" : "+f"(x));
    return x;
}

__device__ __forceinline__ void mma_tf32(float& d0, float& d1, float& d2, float& d3,
                                         uint32_t a0, uint32_t a1, uint32_t a2, uint32_t a3,
                                         uint32_t b0, uint32_t b1) {
    asm volatile(
        "mma.sync.aligned.m16n8k8.row.col.f32.tf32.tf32.f32 "
        "{%0,%1,%2,%3},{%4,%5,%6,%7},{%8,%9},{%0,%1,%2,%3};"
        : "+f"(d0), "+f"(d1), "+f"(d2), "+f"(d3)
        : "r"(a0), "r"(a1), "r"(a2), "r"(a3), "r"(b0), "r"(b1));
}

__device__ __forceinline__ void cp16(uint32_t dst, const void* src) {
    asm volatile("cp.async.cg.shared.global [%0], [%1], 16;" :: "r"(dst), "l"(src));
}
__device__ __forceinline__ void cp_commit() {
    asm volatile("cp.async.commit_group;");
}
__device__ __forceinline__ void cp_wait0() {
    asm volatile("cp.async.wait_group 0;");
}

// ---------------------------------------------------------------------------
// Kernel 2/4: tf32 tensor-core GEMM  C[M,N] = A[M,K] * B[N,K]^T
// mode 0 epilogue: K -> g_k (kperm, tf32), V -> g_vT (transposed, key-perm, tf32)
// mode 1 epilogue: Cout = acc + cbias, A = g_o
// ---------------------------------------------------------------------------
#define GSTR 136

__global__ __launch_bounds__(256, 2)
void gemm_tf32(const float* __restrict__ Ain,
               const float* __restrict__ Bw,
               float* __restrict__ Cout,
               const float* __restrict__ cbias,
               int mode) {
    const float* A = (mode == 1) ? g_o : Ain;

    __shared__ float As[2][16][GSTR];
    __shared__ float Bs[2][16][GSTR];

    const int tid  = threadIdx.x;
    const int warp = tid >> 5;
    const int lane = tid & 31;
    const int qr   = lane >> 2;   // 0..7
    const int qk   = lane & 3;    // 0..3
    const int warpM = (warp & 1) * 64;
    const int warpN = (warp >> 1) * 32;

    const int rowBase = blockIdx.y * 128;
    const int colBase = blockIdx.x * 128;

    const int m0 = tid >> 2;
    const int kq = tid & 3;
    const float* a0p = A  + (size_t)(rowBase + m0) * CDIM + kq * 4;
    const float* a1p = a0p + (size_t)64 * CDIM;
    const float* b0p = Bw + (size_t)(colBase + m0) * CDIM + kq * 4;
    const float* b1p = b0p + (size_t)64 * CDIM;
    const int swS = kq << 3;

    float acc[4][4][4];
#pragma unroll
    for (int mt = 0; mt < 4; mt++)
#pragma unroll
        for (int nt = 0; nt < 4; nt++)
#pragma unroll
            for (int r = 0; r < 4; r++) acc[mt][nt][r] = 0.f;

    float4 ra0, ra1, rb0, rb1;

    ra0 = *(const float4*)(a0p); ra1 = *(const float4*)(a1p);
    rb0 = *(const float4*)(b0p); rb1 = *(const float4*)(b1p);
    {
        float av0[4] = {ra0.x, ra0.y, ra0.z, ra0.w};
        float av1[4] = {ra1.x, ra1.y, ra1.z, ra1.w};
        float bv0[4] = {rb0.x, rb0.y, rb0.z, rb0.w};
        float bv1[4] = {rb1.x, rb1.y, rb1.z, rb1.w};
#pragma unroll
        for (int j = 0; j < 4; j++) {
            As[0][kq * 4 + j][m0 ^ swS]        = to_tf32(av0[j]);
            As[0][kq * 4 + j][(m0 + 64) ^ swS] = to_tf32(av1[j]);
            Bs[0][kq * 4 + j][m0 ^ swS]        = to_tf32(bv0[j]);
            Bs[0][kq * 4 + j][(m0 + 64) ^ swS] = to_tf32(bv1[j]);
        }
    }
    __syncthreads();

    for (int it = 0; it < 32; ++it) {
        const int buf = it & 1;
        if (it < 31) {
            const int off = (it + 1) * 16;
            ra0 = *(const float4*)(a0p + off); ra1 = *(const float4*)(a1p + off);
            rb0 = *(const float4*)(b0p + off); rb1 = *(const float4*)(b1p + off);
        }

#pragma unroll
        for (int ks = 0; ks < 16; ks += 8) {
            uint32_t af[4][4], bf[4][2];
            const int kA = ks + qk;
            const int kB = ks + qk + 4;
            const int sA = ((kA >> 2) << 3);
            const int sB = ((kB >> 2) << 3);
#pragma unroll
            for (int mt = 0; mt < 4; mt++) {
                const int m = warpM + mt * 16 + qr;
                af[mt][0] = __float_as_uint(As[buf][kA][m ^ sA]);
                af[mt][1] = __float_as_uint(As[buf][kA][(m + 8) ^ sA]);
                af[mt][2] = __float_as_uint(As[buf][kB][m ^ sB]);
                af[mt][3] = __float_as_uint(As[buf][kB][(m + 8) ^ sB]);
            }
#pragma unroll
            for (int nt = 0; nt < 4; nt++) {
                const int nn = warpN + nt * 8 + qr;
                bf[nt][0] = __float_as_uint(Bs[buf][kA][nn ^ sA]);
                bf[nt][1] = __float_as_uint(Bs[buf][kB][nn ^ sB]);
            }
#pragma unroll
            for (int mt = 0; mt < 4; mt++)
#pragma unroll
                for (int nt = 0; nt < 4; nt++)
                    mma_tf32(acc[mt][nt][0], acc[mt][nt][1], acc[mt][nt][2], acc[mt][nt][3],
                             af[mt][0], af[mt][1], af[mt][2], af[mt][3],
                             bf[nt][0], bf[nt][1]);
        }

        if (it < 31) {
            const int nbuf = buf ^ 1;
            float av0[4] = {ra0.x, ra0.y, ra0.z, ra0.w};
            float av1[4] = {ra1.x, ra1.y, ra1.z, ra1.w};
            float bv0[4] = {rb0.x, rb0.y, rb0.z, rb0.w};
            float bv1[4] = {rb1.x, rb1.y, rb1.z, rb1.w};
#pragma unroll
            for (int j = 0; j < 4; j++) {
                As[nbuf][kq * 4 + j][m0 ^ swS]        = to_tf32(av0[j]);
                As[nbuf][kq * 4 + j][(m0 + 64) ^ swS] = to_tf32(av1[j]);
                Bs[nbuf][kq * 4 + j][m0 ^ swS]        = to_tf32(bv0[j]);
                Bs[nbuf][kq * 4 + j][(m0 + 64) ^ swS] = to_tf32(bv1[j]);
            }
        }
        __syncthreads();
    }

    if (mode == 0) {
        // K -> g_k (kperm order, tf32-rounded); V -> g_vT (transposed, key-perm, tf32-rounded)
#pragma unroll
        for (int mt = 0; mt < 4; mt++) {
            const int row = rowBase + warpM + mt * 16 + qr;
            const int bb0 = row / NTOK;
            const int nn0 = row - bb0 * NTOK;
            const int bb8 = (row + 8) / NTOK;
            const int nn8 = (row + 8) - bb8 * NTOK;
            const int np0 = (nn0 & ~31) | perm32(nn0 & 31);
            const int np8 = (nn8 & ~31) | perm32(nn8 & 31);
#pragma unroll
            for (int nt = 0; nt < 4; nt++) {
                const int col = colBase + warpN + nt * 8 + qk * 2;
                const int d   = col & 31;
                const float v0 = to_tf32(acc[mt][nt][0]);
                const float v1 = to_tf32(acc[mt][nt][1]);
                const float v2 = to_tf32(acc[mt][nt][2]);
                const float v3 = to_tf32(acc[mt][nt][3]);
                if (col < 512) {
                    const int hv = col >> 5;
                    const int d0p = kperm(d), d1p = kperm(d + 1);
                    size_t base0 = ((((size_t)bb0 * NH + hv) * NTOK) + nn0) * HD;
                    size_t base8 = ((((size_t)bb8 * NH + hv) * NTOK) + nn8) * HD;
                    g_k[base0 + d0p] = v0;  g_k[base0 + d1p] = v1;
                    g_k[base8 + d0p] = v2;  g_k[base8 + d1p] = v3;
                } else {
                    const int hv = (col - 512) >> 5;
                    size_t r0v = (((size_t)bb0 * NH + hv) * HD + d) * VTSTR;
                    size_t r1v = (((size_t)bb0 * NH + hv) * HD + d + 1) * VTSTR;
                    size_t r0w = (((size_t)bb8 * NH + hv) * HD + d) * VTSTR;
                    size_t r1w = (((size_t)bb8 * NH + hv) * HD + d + 1) * VTSTR;
                    g_vT[r0v + np0] = v0;  g_vT[r1v + np0] = v1;
                    g_vT[r0w + np8] = v2;  g_vT[r1w + np8] = v3;
                }
            }
        }
    } else {
#pragma unroll
        for (int mt = 0; mt < 4; mt++) {
            const int row = rowBase + warpM + mt * 16 + qr;
#pragma unroll
            for (int nt = 0; nt < 4; nt++) {
                const int col = colBase + warpN + nt * 8 + qk * 2;
                const float b0v = cbias[col], b1v = cbias[col + 1];
                *(float2*)(Cout + (size_t)row * CDIM + col) =
                    make_float2(acc[mt][nt][0] + b0v, acc[mt][nt][1] + b1v);
                *(float2*)(Cout + (size_t)(row + 8) * CDIM + col) =
                    make_float2(acc[mt][nt][2] + b0v, acc[mt][nt][3] + b1v);
            }
        }
    }
}

// ---------------------------------------------------------------------------
// Kernel 3: tensor-core flash attention, cp.async double-buffered.
// grid (b*h = 2048, 3 query tiles of 128), block 256 (8 warps, 16 q/warp).
// All operand loads are 128-bit: K/V B-frags via LDS.128 (layout-permuted),
// bias/mask via LDG.128 (col-permuted tables). Arithmetic identical to the
// f32/tf32 R12 kernel (bitwise same sums).
// smem: K 2*[64][36] + V^T 2*[32][68] = 35840 B
// ---------------------------------------------------------------------------
#define KSTR 36
#define VSTR 68
#define ATT_SMEM ((2 * 64 * KSTR + 2 * 32 * VSTR) * 4)

__global__ __launch_bounds__(256, 3)
void attn_mma(const float* __restrict__ qg) {
    const int bh = blockIdx.x;
    const int bb = bh >> 4, h = bh & 15;
    const int Bi = bb >> 6, wi = bb & 63;
    const int qbase = blockIdx.y * 128;
    const int tid = threadIdx.x, warp = tid >> 5, lane = tid & 31;
    const int g = lane >> 2, t = lane & 3;

    extern __shared__ float sm[];
    float* KsA[2] = {sm, sm + 64 * KSTR};
    float* VsA[2] = {sm + 2 * 64 * KSTR, sm + 2 * 64 * KSTR + 32 * VSTR};

    const int r0 = qbase + warp * 16 + g;
    const int r1 = r0 + 8;
    const int r0c = min(r0, NTOK - 1), r1c = min(r1, NTOK - 1);

    // Q fragments (registers, pre-scaled), logical k order (unchanged)
    const float* q0p = qg + (((size_t)Bi * NH + h) * NTOK + r0c) * HD;
    const float* q1p = qg + (((size_t)Bi * NH + h) * NTOK + r1c) * HD;
    uint32_t qa[4][4];
#pragma unroll
    for (int ks = 0; ks < 4; ks++) {
        qa[ks][0] = __float_as_uint(to_tf32(q0p[ks * 8 + t] * SCALE_F));
        qa[ks][1] = __float_as_uint(to_tf32(q1p[ks * 8 + t] * SCALE_F));
        qa[ks][2] = __float_as_uint(to_tf32(q0p[ks * 8 + t + 4] * SCALE_F));
        qa[ks][3] = __float_as_uint(to_tf32(q1p[ks * 8 + t + 4] * SCALE_F));
    }

    const float* brow0 = g_bias  + ((size_t)h  * NTOK + r0c) * BMSTR;
    const float* brow1 = g_bias  + ((size_t)h  * NTOK + r1c) * BMSTR;
    const float* mrow0 = g_maskp + ((size_t)wi * NTOK + r0c) * BMSTR;
    const float* mrow1 = g_maskp + ((size_t)wi * NTOK + r1c) * BMSTR;

    const float* kb  = g_k  + ((size_t)bb * NH + h) * NTOK * HD;
    const float* vtb = g_vT + ((size_t)bb * NH + h) * HD * VTSTR;

    // staging: K = 64 rows x 32 floats; V^T = 32 rows x 64 floats
    const int kln = tid >> 2, klp = (tid & 3) * 8;
    const int vrow = tid >> 3, vseg = (tid & 7) * 8;

    const uint32_t ksm[2] = {(uint32_t)__cvta_generic_to_shared(KsA[0] + kln * KSTR + klp),
                             (uint32_t)__cvta_generic_to_shared(KsA[1] + kln * KSTR + klp)};
    const uint32_t vsm[2] = {(uint32_t)__cvta_generic_to_shared(VsA[0] + vrow * VSTR + vseg),
                             (uint32_t)__cvta_generic_to_shared(VsA[1] + vrow * VSTR + vseg)};

    float rm0 = -1e30f, rm1 = -1e30f, l0 = 0.f, l1 = 0.f;
    float oacc[4][4];
#pragma unroll
    for (int df = 0; df < 4; df++)
#pragma unroll
        for (int r = 0; r < 4; r++) oacc[df][r] = 0.f;

    // prologue: stage chunk 0 into buffer 0
    {
        int gn = min(kln, NTOK - 1);
        const float* ksrc = kb + (size_t)gn * HD + klp;
        const float* vsrc = vtb + (size_t)vrow * VTSTR + vseg;
        cp16(ksm[0], ksrc);     cp16(ksm[0] + 16, ksrc + 4);
        cp16(vsm[0], vsrc);     cp16(vsm[0] + 16, vsrc + 4);
        cp_commit();
    }
    cp_wait0();
    __syncthreads();

    for (int c = 0; c < 6; c++) {
        const int buf = c & 1;
        if (c < 5) {
            int gn = min((c + 1) * 64 + kln, NTOK - 1);
            const float* ksrc = kb + (size_t)gn * HD + klp;
            const float* vsrc = vtb + (size_t)vrow * VTSTR + (c + 1) * 64 + vseg;
            const int nb = buf ^ 1;
            cp16(ksm[nb], ksrc);     cp16(ksm[nb] + 16, ksrc + 4);
            cp16(vsm[nb], vsrc);     cp16(vsm[nb] + 16, vsrc + 4);
            cp_commit();
        }
        const float* Ks = KsA[buf];
        const float* Vs = VsA[buf];

#pragma unroll
        for (int h32 = 0; h32 < 2; h32++) {
            const int kb0 = c * 64 + h32 * 32;
            if (kb0 >= NTOK) break;      // fully-masked subchunk contributes exactly 0
            const int nrow0 = h32 * 32;

            // S = Q K^T : per n-frag, ONE pair of LDS.128 covers all 4 k-steps
            float sacc[4][4];
#pragma unroll
            for (int nf = 0; nf < 4; nf++)
#pragma unroll
                for (int r = 0; r < 4; r++) sacc[nf][r] = 0.f;
#pragma unroll
            for (int nf = 0; nf < 4; nf++) {
                const float* kr = &Ks[(nrow0 + nf * 8 + g) * KSTR + t * 8];
                float4 k01 = *(const float4*)(kr);
                float4 k23 = *(const float4*)(kr + 4);
                mma_tf32(sacc[nf][0], sacc[nf][1], sacc[nf][2], sacc[nf][3],
                         qa[0][0], qa[0][1], qa[0][2], qa[0][3],
                         __float_as_uint(k01.x), __float_as_uint(k01.y));
                mma_tf32(sacc[nf][0], sacc[nf][1], sacc[nf][2], sacc[nf][3],
                         qa[1][0], qa[1][1], qa[1][2], qa[1][3],
                         __float_as_uint(k01.z), __float_as_uint(k01.w));
                mma_tf32(sacc[nf][0], sacc[nf][1], sacc[nf][2], sacc[nf][3],
                         qa[2][0], qa[2][1], qa[2][2], qa[2][3],
                         __float_as_uint(k23.x), __float_as_uint(k23.y));
                mma_tf32(sacc[nf][0], sacc[nf][1], sacc[nf][2], sacc[nf][3],
                         qa[3][0], qa[3][1], qa[3][2], qa[3][3],
                         __float_as_uint(k23.z), __float_as_uint(k23.w));
            }

            // + bias + mask via col-permuted LDG.128 (X[2*nf+b] = col kb0+8nf+2t+b)
            float B0[8], M0[8], B1[8], M1[8];
            {
                float4 a, b;
                a = *(const float4*)(brow0 + kb0 + t * 8);
                b = *(const float4*)(brow0 + kb0 + t * 8 + 4);
                B0[0]=a.x; B0[1]=a.y; B0[2]=a.z; B0[3]=a.w;
                B0[4]=b.x; B0[5]=b.y; B0[6]=b.z; B0[7]=b.w;
                a = *(const float4*)(mrow0 + kb0 + t * 8);
                b = *(const float4*)(mrow0 + kb0 + t * 8 + 4);
                M0[0]=a.x; M0[1]=a.y; M0[2]=a.z; M0[3]=a.w;
                M0[4]=b.x; M0[5]=b.y; M0[6]=b.z; M0[7]=b.w;
                a = *(const float4*)(brow1 + kb0 + t * 8);
                b = *(const float4*)(brow1 + kb0 + t * 8 + 4);
                B1[0]=a.x; B1[1]=a.y; B1[2]=a.z; B1[3]=a.w;
                B1[4]=b.x; B1[5]=b.y; B1[6]=b.z; B1[7]=b.w;
                a = *(const float4*)(mrow1 + kb0 + t * 8);
                b = *(const float4*)(mrow1 + kb0 + t * 8 + 4);
                M1[0]=a.x; M1[1]=a.y; M1[2]=a.z; M1[3]=a.w;
                M1[4]=b.x; M1[5]=b.y; M1[6]=b.z; M1[7]=b.w;
            }
            float cm0 = -1e30f, cm1 = -1e30f;
#pragma unroll
            for (int nf = 0; nf < 4; nf++) {
                int col = kb0 + nf * 8 + 2 * t;
                sacc[nf][0] = (col     < NTOK) ? sacc[nf][0] + B0[2*nf]   + M0[2*nf]   : -1e30f;
                sacc[nf][1] = (col + 1 < NTOK) ? sacc[nf][1] + B0[2*nf+1] + M0[2*nf+1] : -1e30f;
                sacc[nf][2] = (col     < NTOK) ? sacc[nf][2] + B1[2*nf]   + M1[2*nf]   : -1e30f;
                sacc[nf][3] = (col + 1 < NTOK) ? sacc[nf][3] + B1[2*nf+1] + M1[2*nf+1] : -1e30f;
                cm0 = fmaxf(cm0, fmaxf(sacc[nf][0], sacc[nf][1]));
                cm1 = fmaxf(cm1, fmaxf(sacc[nf][2], sacc[nf][3]));
            }
            cm0 = fmaxf(cm0, __shfl_xor_sync(0xffffffffu, cm0, 1));
            cm0 = fmaxf(cm0, __shfl_xor_sync(0xffffffffu, cm0, 2));
            cm1 = fmaxf(cm1, __shfl_xor_sync(0xffffffffu, cm1, 1));
            cm1 = fmaxf(cm1, __shfl_xor_sync(0xffffffffu, cm1, 2));

            float mn0 = fmaxf(rm0, cm0), mn1 = fmaxf(rm1, cm1);
            float sc0 = __expf(rm0 - mn0), sc1 = __expf(rm1 - mn1);
            rm0 = mn0; rm1 = mn1;

            // exp in-place; P stays in registers as PV A-fragments
            float ls0 = 0.f, ls1 = 0.f;
#pragma unroll
            for (int nf = 0; nf < 4; nf++) {
                float p0 = __expf(sacc[nf][0] - mn0);
                float p1 = __expf(sacc[nf][1] - mn0);
                float p2 = __expf(sacc[nf][2] - mn1);
                float p3 = __expf(sacc[nf][3] - mn1);
                ls0 += p0 + p1; ls1 += p2 + p3;
                sacc[nf][0] = to_tf32(p0);
                sacc[nf][1] = to_tf32(p1);
                sacc[nf][2] = to_tf32(p2);
                sacc[nf][3] = to_tf32(p3);
            }
            ls0 += __shfl_xor_sync(0xffffffffu, ls0, 1);
            ls0 += __shfl_xor_sync(0xffffffffu, ls0, 2);
            ls1 += __shfl_xor_sync(0xffffffffu, ls1, 1);
            ls1 += __shfl_xor_sync(0xffffffffu, ls1, 2);
            l0 = l0 * sc0 + ls0;
            l1 = l1 * sc1 + ls1;

#pragma unroll
            for (int df = 0; df < 4; df++) {
                oacc[df][0] *= sc0; oacc[df][1] *= sc0;
                oacc[df][2] *= sc1; oacc[df][3] *= sc1;
            }

            // O += P V : per d-frag, ONE pair of LDS.128 covers all 4 k-steps
            uint32_t au[4][4];
#pragma unroll
            for (int ks = 0; ks < 4; ks++) {
                au[ks][0] = __float_as_uint(sacc[ks][0]);
                au[ks][1] = __float_as_uint(sacc[ks][2]);
                au[ks][2] = __float_as_uint(sacc[ks][1]);
                au[ks][3] = __float_as_uint(sacc[ks][3]);
            }
#pragma unroll
            for (int df = 0; df < 4; df++) {
                const float* vr = &Vs[(df * 8 + g) * VSTR + nrow0 + t * 8];
                float4 v01 = *(const float4*)(vr);
                float4 v23 = *(const float4*)(vr + 4);
                mma_tf32(oacc[df][0], oacc[df][1], oacc[df][2], oacc[df][3],
                         au[0][0], au[0][1], au[0][2], au[0][3],
                         __float_as_uint(v01.x), __float_as_uint(v01.y));
                mma_tf32(oacc[df][0], oacc[df][1], oacc[df][2], oacc[df][3],
                         au[1][0], au[1][1], au[1][2], au[1][3],
                         __float_as_uint(v01.z), __float_as_uint(v01.w));
                mma_tf32(oacc[df][0], oacc[df][1], oacc[df][2], oacc[df][3],
                         au[2][0], au[2][1], au[2][2], au[2][3],
                         __float_as_uint(v23.x), __float_as_uint(v23.y));
                mma_tf32(oacc[df][0], oacc[df][1], oacc[df][2], oacc[df][3],
                         au[3][0], au[3][1], au[3][2], au[3][3],
                         __float_as_uint(v23.z), __float_as_uint(v23.w));
            }
        }

        if (c < 5) cp_wait0();
        __syncthreads();
    }

    // epilogue: normalize + store
    float inv0 = 1.f / l0, inv1 = 1.f / l1;
    if (r0 < NTOK) {
        float* orow = g_o + ((size_t)bb * NTOK + r0) * CDIM + h * HD;
#pragma unroll
        for (int df = 0; df < 4; df++)
            *(float2*)(orow + df * 8 + 2 * t) =
                make_float2(oacc[df][0] * inv0, oacc[df][1] * inv0);
    }
    if (r1 < NTOK) {
        float* orow = g_o + ((size_t)bb * NTOK + r1) * CDIM + h * HD;
#pragma unroll
        for (int df = 0; df < 4; df++)
            *(float2*)(orow + df * 8 + 2 * t) =
                make_float2(oacc[df][2] * inv1, oacc[df][3] * inv1);
    }
}

// ---------------------------------------------------------------------------
// Launch
// ---------------------------------------------------------------------------
extern "C" void kernel_launch(void* const* d_in, const int* in_sizes, int n_in,
                              void* d_out, int out_size) {
    const float* x      = (const float*)d_in[0];
    // d_in[1..3] = D,H,W scalars (constant 7) — unused
    const float* mask   = (const float*)d_in[4];
    const float* qg     = (const float*)d_in[5];
    const float* kv_w   = (const float*)d_in[6];
    const float* proj_w = (const float*)d_in[7];
    const float* proj_b = (const float*)d_in[8];
    const float* rpb    = (const float*)d_in[9];
    float* out = (float*)d_out;

    cudaFuncSetAttribute(attn_mma, cudaFuncAttributeMaxDynamicSharedMemorySize, ATT_SMEM);

    // 1) padded, col-permuted bias + mask tables (f32)
    bias_kernel<<<(NTOK * BMSTR + 255) / 256, 256>>>(rpb);
    mask_copy_kernel<<<(64 * NTOK * BMSTR + 255) / 256, 256>>>(mask);

    // 2) KV projection: [43904,512] x [1024,512]^T -> g_k (kperm) / g_vT (key-perm)
    gemm_tf32<<<dim3(1024 / 128, MROWS / 128), 256>>>(x, kv_w, nullptr, nullptr, 0);

    // 3) tensor-core flash attention -> g_o
    attn_mma<<<dim3(NB * NH, 3), 256, ATT_SMEM>>>(qg);

    // 4) output projection: [43904,512] x [512,512]^T + bias -> d_out (tf32 MMA)
    gemm_tf32<<<dim3(CDIM / 128, MROWS / 128), 256>>>(nullptr, proj_w, out, proj_b, 1);
}